// round 1
// baseline (speedup 1.0000x reference)
#include <cuda_runtime.h>
#include <math.h>

#define NB 1024
#define CCH 62
#define PC 64
#define NBAND 5
#define SLICE (CCH*PC)          // 3968
#define NELEM (NBAND*CCH*CCH)   // 19220
#define NTH 256
#define NOUT 16

// shared memory layout (floats)
#define OFF_COM 19840
#define OFF_W   39680
#define OFF_H   43776
#define OFF_E   47744
#define OFF_SMALL 51712
#define SMEM_FLOATS 54832
#define SMEM_BYTES (SMEM_FLOATS*4)

__device__ float g_z[NB*CCH];
__device__ float g_stats[128];

__device__ __forceinline__ float sigmoidf_(float x){ return 1.f/(1.f+expf(-x)); }

// ---------------------------------------------------------------------------
// branch: z[k,i,o] = sigmoid( cw[k]*(com[k]@lwT)[i,o] + cb[k]*rowsum(lw)[o] + lb[o] )
// then attention over bands -> outbuf[62][64]
// ---------------------------------------------------------------------------
__device__ __forceinline__ void run_branch(
    const float* __restrict__ lin_w, const float* __restrict__ lin_b,
    const float* __restrict__ cw, const float* __restrict__ cb,
    float* xbuf, float* com, float* wbuf,
    float* sbuf, float* bbuf, float* rowsum, float* lbbuf,
    float* w1s, float* b1s, float* w2s,
    float* outbuf, int tid, int tx, int ty)
{
  // load weights (zero-padded 64x64)
  for (int idx = tid; idx < PC*PC; idx += NTH) wbuf[idx] = 0.f;
  __syncthreads();
  for (int idx = tid; idx < CCH*CCH; idx += NTH) {
    int o = idx / CCH, c = idx - o*CCH;
    wbuf[o*PC + c] = lin_w[idx];
  }
  if (tid < CCH) lbbuf[tid] = lin_b[tid];
  __syncthreads();
  if (tid < CCH) {
    float s = 0.f;
    for (int c = 0; c < CCH; c++) s += wbuf[tid*PC + c];
    rowsum[tid] = s;
  }
  __syncthreads();

  // per-band GEMM + sigmoid epilogue -> z stored in xbuf
  for (int k = 0; k < NBAND; k++) {
    float cwk = cw[k], cbk = cb[k];
    const float* ck = com + k*SLICE;
    float acc[16];
    #pragma unroll
    for (int u = 0; u < 16; u++) acc[u] = 0.f;
    #pragma unroll 4
    for (int c0 = 0; c0 < PC; c0 += 4) {
      float4 a[4], bb[4];
      #pragma unroll
      for (int r = 0; r < 4; r++) a[r] = *(const float4*)(ck + (ty*4+r)*PC + c0);
      #pragma unroll
      for (int q = 0; q < 4; q++) bb[q] = *(const float4*)(wbuf + (tx*4+q)*PC + c0);
      #pragma unroll
      for (int r = 0; r < 4; r++) {
        #pragma unroll
        for (int q = 0; q < 4; q++) {
          acc[r*4+q] = fmaf(a[r].x, bb[q].x, acc[r*4+q]);
          acc[r*4+q] = fmaf(a[r].y, bb[q].y, acc[r*4+q]);
          acc[r*4+q] = fmaf(a[r].z, bb[q].z, acc[r*4+q]);
          acc[r*4+q] = fmaf(a[r].w, bb[q].w, acc[r*4+q]);
        }
      }
    }
    #pragma unroll
    for (int r = 0; r < 4; r++) {
      int i = ty*4 + r;
      if (i < CCH) {
        #pragma unroll
        for (int q = 0; q < 4; q++) {
          int o = tx*4 + q;
          if (o < CCH) {
            float zz = cwk*acc[r*4+q] + cbk*rowsum[o] + lbbuf[o];
            xbuf[k*SLICE + i*PC + o] = sigmoidf_(zz);
          }
        }
      }
    }
  }
  __syncthreads();

  // attention scores per (k,i)
  for (int r = tid; r < NBAND*CCH; r += NTH) {
    int k = r / CCH, i = r - k*CCH;
    const float* zrow = xbuf + k*SLICE + i*PC;
    float hacc[10];
    #pragma unroll
    for (int t = 0; t < 10; t++) hacc[t] = 0.f;
    for (int c = 0; c < CCH; c++) {
      float zv = zrow[c];
      #pragma unroll
      for (int t = 0; t < 10; t++) hacc[t] = fmaf(zv, w1s[t*CCH + c], hacc[t]);
    }
    float sc = 0.f;
    #pragma unroll
    for (int t = 0; t < 10; t++) sc = fmaf(tanhf(hacc[t] + b1s[t]), w2s[t], sc);
    sbuf[k*PC + i] = sc;
  }
  __syncthreads();
  if (tid < CCH) {
    float s[NBAND], m = -1e30f;
    #pragma unroll
    for (int k = 0; k < NBAND; k++) { s[k] = sbuf[k*PC + tid]; m = fmaxf(m, s[k]); }
    float ssum = 0.f;
    #pragma unroll
    for (int k = 0; k < NBAND; k++) { s[k] = expf(s[k] - m); ssum += s[k]; }
    float inv = 1.f/ssum;
    #pragma unroll
    for (int k = 0; k < NBAND; k++) bbuf[k*PC + tid] = s[k]*inv;
  }
  __syncthreads();
  for (int idx = tid; idx < CCH*CCH; idx += NTH) {
    int i = idx / CCH, c = idx - i*CCH;
    float acc = 0.f;
    #pragma unroll
    for (int k = 0; k < NBAND; k++) acc = fmaf(bbuf[k*PC + i], xbuf[k*SLICE + i*PC + c], acc);
    outbuf[i*PC + c] = acc;
  }
  __syncthreads();
}

__global__ __launch_bounds__(NTH, 1) void main_kernel(
  const float* __restrict__ de, const float* __restrict__ pcc, const float* __restrict__ Aadj,
  const float* __restrict__ conv_w, const float* __restrict__ conv_b,
  const float* __restrict__ hconv_w, const float* __restrict__ hconv_b,
  const float* __restrict__ hlin_w, const float* __restrict__ hlin_b,
  const float* __restrict__ econv_w, const float* __restrict__ econv_b,
  const float* __restrict__ elin_w, const float* __restrict__ elin_b,
  const float* __restrict__ att_w1, const float* __restrict__ att_b1, const float* __restrict__ att_w2,
  const float* __restrict__ gc_w, const float* __restrict__ gc_b,
  const float* __restrict__ fc_w, const float* __restrict__ fc_b)
{
  extern __shared__ float sm[];
  float* xbuf = sm;
  float* com  = sm + OFF_COM;
  float* wbuf = sm + OFF_W;
  float* hbuf = sm + OFF_H;
  float* ebuf = sm + OFF_E;
  float* small = sm + OFF_SMALL;
  float* gbuf   = small;          // 8
  float* scal   = small + 8;      // 8
  float* mubuf  = small + 16;     // 64
  float* sbuf   = small + 80;     // 320
  float* bbuf   = small + 400;    // 320
  float* rowsum = small + 720;    // 64
  float* w1s    = small + 784;    // 640
  float* b1s    = small + 1424;   // 16
  float* w2s    = small + 1440;   // 16
  float* lbbuf  = small + 1456;   // 64
  float* red    = small + 1520;   // 1280
  float* debuf  = small + 2800;   // 320
  // aliases (wbuf is free after the branch GEMMs)
  float* xg0  = wbuf;
  float* xg1  = wbuf + 992;
  float* fbuf = wbuf + 1984;

  const int b = blockIdx.x;
  const int tid = threadIdx.x;
  const int tx = tid & 15, ty = tid >> 4;

  if (tid < 10) { b1s[tid] = att_b1[tid]; w2s[tid] = att_w2[tid]; }
  for (int i = tid; i < 10*CCH; i += NTH) w1s[i] = att_w1[i];

  // ==== two phases: 0 = sadj (A), 1 = fadj (transposed pcc) ====
  for (int phase = 0; phase < 2; phase++) {
    if (phase == 0) {
      const float* src = Aadj + (size_t)b * NELEM;
      for (int e = tid; e < NELEM; e += NTH) {
        int k = e / (CCH*CCH); int r = e - k*CCH*CCH; int h = r / CCH; int w = r - h*CCH;
        xbuf[k*SLICE + h*PC + w] = src[e];
      }
    } else {
      const float* src = pcc + (size_t)b * NELEM;
      for (int e = tid; e < NELEM; e += NTH) {
        int k = e % NBAND; int hw = e / NBAND; int h = hw / CCH; int w = hw - h*CCH;
        xbuf[k*SLICE + h*PC + w] = src[e];
      }
    }
    for (int i = tid; i < NBAND*CCH; i += NTH) {
      int k = i / CCH, h = i - k*CCH;
      xbuf[k*SLICE + h*PC + 62] = 0.f;
      xbuf[k*SLICE + h*PC + 63] = 0.f;
    }
    __syncthreads();

    // gate scores s[o] = sum_e x[e]*conv_w[o][e]
    float sl[NBAND] = {0.f,0.f,0.f,0.f,0.f};
    for (int e = tid; e < NELEM; e += NTH) {
      int i = e / (CCH*CCH); int r = e - i*CCH*CCH; int h = r / CCH; int w = r - h*CCH;
      float xv = xbuf[i*SLICE + h*PC + w];
      #pragma unroll
      for (int o = 0; o < NBAND; o++) sl[o] = fmaf(xv, conv_w[o*NELEM + e], sl[o]);
    }
    #pragma unroll
    for (int o = 0; o < NBAND; o++) red[o*NTH + tid] = sl[o];
    __syncthreads();
    for (int off = NTH/2; off > 0; off >>= 1) {
      if (tid < off) {
        #pragma unroll
        for (int o = 0; o < NBAND; o++) red[o*NTH + tid] += red[o*NTH + tid + off];
      }
      __syncthreads();
    }
    if (tid == 0) {
      float s[NBAND], m = -1e30f;
      #pragma unroll
      for (int o = 0; o < NBAND; o++) { s[o] = red[o*NTH] + conv_b[o]; m = fmaxf(m, s[o]); }
      float ssum = 0.f;
      #pragma unroll
      for (int o = 0; o < NBAND; o++) { s[o] = expf(s[o]-m); ssum += s[o]; }
      float inv = 1.f/ssum;
      #pragma unroll
      for (int o = 0; o < NBAND; o++) gbuf[o] = s[o]*inv;
    }
    __syncthreads();

    // per-band: gated relu, center rows, Gram, trace-normalize, accumulate com
    for (int k = 0; k < NBAND; k++) {
      float gk = gbuf[k];
      float* xk = xbuf + k*SLICE;
      for (int idx = tid; idx < CCH*CCH; idx += NTH) {
        int i = idx / CCH, w = idx - i*CCH;
        xk[i*PC + w] = fmaxf(gk * xk[i*PC + w], 0.f);
      }
      __syncthreads();
      if (tid < CCH) {
        float s = 0.f;
        for (int w = 0; w < CCH; w++) s += xk[tid*PC + w];
        mubuf[tid] = s * (1.f/62.f);
      }
      __syncthreads();
      for (int idx = tid; idx < CCH*CCH; idx += NTH) {
        int i = idx / CCH, w = idx - i*CCH;
        xk[i*PC + w] -= mubuf[i];
      }
      __syncthreads();
      // Gram: wbuf[j][l] = sum_i xk[i][j]*xk[i][l]  (raw; /61 cancels in trace norm)
      float acc[16];
      #pragma unroll
      for (int u = 0; u < 16; u++) acc[u] = 0.f;
      #pragma unroll 2
      for (int i = 0; i < CCH; i++) {
        float4 av = *(const float4*)(xk + i*PC + ty*4);
        float4 bv = *(const float4*)(xk + i*PC + tx*4);
        float ar[4] = {av.x, av.y, av.z, av.w};
        float br[4] = {bv.x, bv.y, bv.z, bv.w};
        #pragma unroll
        for (int r = 0; r < 4; r++) {
          #pragma unroll
          for (int q = 0; q < 4; q++)
            acc[r*4+q] = fmaf(ar[r], br[q], acc[r*4+q]);
        }
      }
      #pragma unroll
      for (int r = 0; r < 4; r++) {
        #pragma unroll
        for (int q = 0; q < 4; q++)
          wbuf[(ty*4+r)*PC + tx*4 + q] = acc[r*4+q];
      }
      __syncthreads();
      if (tid < 32) {
        float t = wbuf[tid*PC + tid];
        if (tid + 32 < CCH) t += wbuf[(tid+32)*PC + (tid+32)];
        #pragma unroll
        for (int off = 16; off > 0; off >>= 1)
          t += __shfl_xor_sync(0xffffffffu, t, off);
        if (tid == 0) scal[0] = 1.f / t;
      }
      __syncthreads();
      float invt = scal[0];
      float* comk = com + k*SLICE;
      if (phase == 0) {
        for (int idx = tid; idx < SLICE; idx += NTH) {
          int j = idx >> 6, l = idx & 63;
          comk[idx] = 0.5f*(wbuf[idx]*invt + ((j==l) ? 1e-5f : 0.f));
        }
      } else {
        for (int idx = tid; idx < SLICE; idx += NTH) {
          int j = idx >> 6, l = idx & 63;
          comk[idx] += 0.5f*(wbuf[idx]*invt + ((j==l) ? 1e-5f : 0.f));
        }
      }
      __syncthreads();
    }
  }

  // ==== hidden / essential branches + attention ====
  run_branch(hlin_w, hlin_b, hconv_w, hconv_b, xbuf, com, wbuf,
             sbuf, bbuf, rowsum, lbbuf, w1s, b1s, w2s, hbuf, tid, tx, ty);
  run_branch(elin_w, elin_b, econv_w, econv_b, xbuf, com, wbuf,
             sbuf, bbuf, rowsum, lbbuf, w1s, b1s, w2s, ebuf, tid, tx, ty);

  // ==== Chebyshev GCN + fc ====
  for (int i = tid; i < CCH*NBAND; i += NTH) debuf[i] = de[(size_t)b*CCH*NBAND + i];
  __syncthreads();
  for (int idx = tid; idx < CCH*NOUT; idx += NTH) {
    int i = idx / NOUT, f = idx - i*NOUT;
    float a0 = 0.f, a1 = 0.f;
    #pragma unroll
    for (int t = 0; t < NBAND; t++) {
      float dv = debuf[i*NBAND + t];
      a0 = fmaf(dv, gc_w[t*NOUT + f], a0);
      a1 = fmaf(dv, gc_w[(NBAND + t)*NOUT + f], a1);
    }
    xg0[idx] = a0; xg1[idx] = a1;
  }
  __syncthreads();
  for (int idx = tid; idx < CCH*NOUT; idx += NTH) {
    int i = idx / NOUT, f = idx - i*NOUT;
    float base = xg0[idx] + gc_b[f] + gc_b[NOUT + f];
    float ah = 0.f, ae = 0.f;
    for (int j = 0; j < CCH; j++) {
      float v = xg1[j*NOUT + f];
      ah = fmaf(hbuf[i*PC + j], v, ah);
      ae = fmaf(ebuf[i*PC + j], v, ae);
    }
    float hv = fmaxf(base + ah, 0.f);
    float ev = fmaxf(base + ae, 0.f);
    fbuf[idx] = fmaxf(0.5f*(hv + ev), 0.f);   // wnorm == 1 (softmax over 1 element)
  }
  __syncthreads();
  if (tid < CCH) {
    float acc = fc_b[tid];
    const float* wrow = fc_w + (size_t)tid * (CCH*NOUT);
    #pragma unroll 4
    for (int q = 0; q < CCH*NOUT; q++) acc = fmaf(fbuf[q], wrow[q], acc);
    g_z[b*CCH + tid] = acc;
  }
}

// ==== batch-norm statistics over the batch dimension ====
__global__ __launch_bounds__(NTH) void stats_kernel() {
  __shared__ double rs[NTH], rs2[NTH];
  int c = blockIdx.x, tid = threadIdx.x;
  double s = 0.0, s2 = 0.0;
  for (int bb = tid; bb < NB; bb += NTH) {
    double v = (double)g_z[bb*CCH + c];
    s += v; s2 += v*v;
  }
  rs[tid] = s; rs2[tid] = s2;
  __syncthreads();
  for (int off = NTH/2; off > 0; off >>= 1) {
    if (tid < off) { rs[tid] += rs[tid+off]; rs2[tid] += rs2[tid+off]; }
    __syncthreads();
  }
  if (tid == 0) {
    double m = rs[0] / NB;
    double var = rs2[0] / NB - m*m;
    g_stats[c] = (float)m;
    g_stats[64 + c] = (float)(1.0 / sqrt(var + 1e-5));
  }
}

// ==== normalize + sigmoid + 2-wide head ====
__global__ __launch_bounds__(64) void final_kernel(
  const float* __restrict__ bn_g, const float* __restrict__ bn_b,
  const float* __restrict__ fc4_w, const float* __restrict__ fc4_b,
  float* __restrict__ out)
{
  __shared__ float o1[64];
  int b = blockIdx.x, tid = threadIdx.x;
  if (tid < CCH) {
    float z = g_z[b*CCH + tid];
    float zn = (z - g_stats[tid]) * g_stats[64 + tid] * bn_g[tid] + bn_b[tid];
    float v = sigmoidf_(zn);
    out[b*CCH + tid] = v;
    o1[tid] = v;
  }
  __syncthreads();
  if (tid < 2) {
    float acc = fc4_b[tid];
    for (int c = 0; c < CCH; c++) acc = fmaf(o1[c], fc4_w[tid*CCH + c], acc);
    out[NB*CCH + b*2 + tid] = acc;
  }
}

extern "C" void kernel_launch(void* const* d_in, const int* in_sizes, int n_in,
                              void* d_out, int out_size) {
  const float* de     = (const float*)d_in[0];
  const float* pcc    = (const float*)d_in[1];
  const float* Aadj   = (const float*)d_in[2];
  const float* conv_w = (const float*)d_in[3];
  const float* conv_b = (const float*)d_in[4];
  const float* hconv_w= (const float*)d_in[5];
  const float* hconv_b= (const float*)d_in[6];
  const float* hlin_w = (const float*)d_in[7];
  const float* hlin_b = (const float*)d_in[8];
  const float* econv_w= (const float*)d_in[9];
  const float* econv_b= (const float*)d_in[10];
  const float* elin_w = (const float*)d_in[11];
  const float* elin_b = (const float*)d_in[12];
  const float* att_w1 = (const float*)d_in[13];
  const float* att_b1 = (const float*)d_in[14];
  const float* att_w2 = (const float*)d_in[15];
  const float* gc_w   = (const float*)d_in[16];
  const float* gc_b   = (const float*)d_in[17];
  /* d_in[18] = wpar: softmax over a single element == 1, folded out */
  const float* fc_w   = (const float*)d_in[19];
  const float* fc_b   = (const float*)d_in[20];
  const float* bn_g   = (const float*)d_in[21];
  const float* bn_b   = (const float*)d_in[22];
  const float* fc4_w  = (const float*)d_in[23];
  const float* fc4_b  = (const float*)d_in[24];

  cudaFuncSetAttribute(main_kernel, cudaFuncAttributeMaxDynamicSharedMemorySize, SMEM_BYTES);

  main_kernel<<<NB, NTH, SMEM_BYTES>>>(
      de, pcc, Aadj, conv_w, conv_b,
      hconv_w, hconv_b, hlin_w, hlin_b,
      econv_w, econv_b, elin_w, elin_b,
      att_w1, att_b1, att_w2, gc_w, gc_b, fc_w, fc_b);
  stats_kernel<<<CCH, NTH>>>();
  final_kernel<<<NB, 64>>>(bn_g, bn_b, fc4_w, fc4_b, (float*)d_out);
}

// round 12
// speedup vs baseline: 1.6302x; 1.6302x over previous
#include <cuda_runtime.h>
#include <cuda_fp16.h>
#include <math.h>

#define NB 1024
#define CCH 62
#define PC 64
#define NBAND 5
#define HW 3844              // 62*62
#define NELEM 19220          // 5*3844
#define NOUT 16
#define NTH 256

// ---------------- device scratch ----------------
__device__ float g_wP[NBAND*NELEM];        // conv_w permuted: [o][hw][k]
__device__ float g_gain0[NB*NBAND];        // softmax gate for A (sadj)
__device__ float g_gain1[NB*NBAND];        // softmax gate for pcc (fadj)
__device__ float g_com[(size_t)NB*NBAND*CCH*PC];   // [b][k][62][64]
__device__ float g_att[(size_t)NB*2*HW];           // [b][branch][62*62]
__device__ float g_z[NB*CCH];
__device__ float g_stats[128];

__device__ __forceinline__ float sigmoidf_(float x){ return 1.f/(1.f+expf(-x)); }

// ---------------- K0: permute conv_w -> [o][hw][k] ----------------
__global__ void permw_kernel(const float* __restrict__ conv_w) {
  int idx = blockIdx.x*NTH + threadIdx.x;
  if (idx < NBAND*NELEM) {
    int o = idx / NELEM; int r = idx - o*NELEM;
    int k = r / HW; int hw = r - k*HW;
    g_wP[o*NELEM + hw*NBAND + k] = conv_w[idx];
  }
}

// ---------------- K1: gate scores + softmax (both adjacencies) ----------------
__global__ __launch_bounds__(NTH) void gate_kernel(
    const float* __restrict__ A, const float* __restrict__ pcc,
    const float* __restrict__ conv_w, const float* __restrict__ conv_b) {
  __shared__ float red[10*NTH];
  int b = blockIdx.x, tid = threadIdx.x;
  const float4* xA = (const float4*)(A  + (size_t)b*NELEM);
  const float4* xP = (const float4*)(pcc + (size_t)b*NELEM);
  float s[10];
  #pragma unroll
  for (int o = 0; o < 10; o++) s[o] = 0.f;
  for (int e = tid; e < NELEM/4; e += NTH) {
    float4 xa = xA[e];
    float4 xp = xP[e];
    #pragma unroll
    for (int o = 0; o < 5; o++) {
      float4 wa = ((const float4*)(conv_w + o*NELEM))[e];
      s[o] = fmaf(xa.x, wa.x, s[o]); s[o] = fmaf(xa.y, wa.y, s[o]);
      s[o] = fmaf(xa.z, wa.z, s[o]); s[o] = fmaf(xa.w, wa.w, s[o]);
      float4 wp = ((const float4*)(g_wP + o*NELEM))[e];
      s[5+o] = fmaf(xp.x, wp.x, s[5+o]); s[5+o] = fmaf(xp.y, wp.y, s[5+o]);
      s[5+o] = fmaf(xp.z, wp.z, s[5+o]); s[5+o] = fmaf(xp.w, wp.w, s[5+o]);
    }
  }
  #pragma unroll
  for (int o = 0; o < 10; o++) red[o*NTH + tid] = s[o];
  __syncthreads();
  for (int off = NTH/2; off >= 1; off >>= 1) {
    if (tid < off) {
      #pragma unroll
      for (int o = 0; o < 10; o++) red[o*NTH + tid] += red[o*NTH + tid + off];
    }
    __syncthreads();
  }
  if (tid == 0) {
    float v[5], m, ssum, inv;
    m = -1e30f;
    #pragma unroll
    for (int o = 0; o < 5; o++) { v[o] = red[o*NTH] + conv_b[o]; m = fmaxf(m, v[o]); }
    ssum = 0.f;
    #pragma unroll
    for (int o = 0; o < 5; o++) { v[o] = expf(v[o]-m); ssum += v[o]; }
    inv = 1.f/ssum;
    #pragma unroll
    for (int o = 0; o < 5; o++) g_gain0[b*NBAND+o] = v[o]*inv;
    m = -1e30f;
    #pragma unroll
    for (int o = 0; o < 5; o++) { v[o] = red[(5+o)*NTH] + conv_b[o]; m = fmaxf(m, v[o]); }
    ssum = 0.f;
    #pragma unroll
    for (int o = 0; o < 5; o++) { v[o] = expf(v[o]-m); ssum += v[o]; }
    inv = 1.f/ssum;
    #pragma unroll
    for (int o = 0; o < 5; o++) g_gain1[b*NBAND+o] = v[o]*inv;
  }
}

// ---------------- K2: gated relu -> center -> Gram -> trace-norm -> com ----------------
__global__ __launch_bounds__(NTH) void com_kernel(
    const float* __restrict__ A, const float* __restrict__ pcc) {
  __shared__ float xk[CCH*PC];
  __shared__ float mubuf[CCH];
  __shared__ float trbuf[16];
  __shared__ float scal;
  int bid = blockIdx.x;
  int b = bid / NBAND, k = bid - b*NBAND;
  int tid = threadIdx.x, tx = tid & 15, ty = tid >> 4;

  float comacc[16];
  #pragma unroll
  for (int u = 0; u < 16; u++) comacc[u] = 0.f;

  for (int phase = 0; phase < 2; phase++) {
    float g = phase ? g_gain1[b*NBAND+k] : g_gain0[b*NBAND+k];
    if (phase == 0) {
      const float* src = A + (size_t)b*NELEM + k*HW;
      for (int idx = tid; idx < HW; idx += NTH) {
        int h = idx / CCH, w = idx - h*CCH;
        xk[h*PC + w] = fmaxf(g*src[idx], 0.f);
      }
    } else {
      const float* src = pcc + (size_t)b*NELEM + k;
      for (int idx = tid; idx < HW; idx += NTH) {
        int h = idx / CCH, w = idx - h*CCH;
        xk[h*PC + w] = fmaxf(g*src[idx*NBAND], 0.f);
      }
    }
    if (tid < 2*CCH) { int h = tid >> 1; xk[h*PC + 62 + (tid & 1)] = 0.f; }
    __syncthreads();
    if (tid < CCH) {
      float ssum = 0.f;
      #pragma unroll 2
      for (int w = 0; w < CCH; w++) ssum += xk[tid*PC + w];
      mubuf[tid] = ssum * (1.f/62.f);
    }
    __syncthreads();
    for (int idx = tid; idx < HW; idx += NTH) {
      int h = idx / CCH, w = idx - h*CCH;
      xk[h*PC + w] -= mubuf[h];
    }
    __syncthreads();

    float acc[16];
    #pragma unroll
    for (int u = 0; u < 16; u++) acc[u] = 0.f;
    #pragma unroll 2
    for (int i = 0; i < CCH; i++) {
      float4 av = *(const float4*)(xk + i*PC + ty*4);
      float4 bv = *(const float4*)(xk + i*PC + tx*4);
      float ar[4] = {av.x, av.y, av.z, av.w};
      float br[4] = {bv.x, bv.y, bv.z, bv.w};
      #pragma unroll
      for (int r = 0; r < 4; r++)
        #pragma unroll
        for (int q = 0; q < 4; q++)
          acc[r*4+q] = fmaf(ar[r], br[q], acc[r*4+q]);
    }
    if (tx == ty) trbuf[ty] = acc[0] + acc[5] + acc[10] + acc[15];
    __syncthreads();
    if (tid < 16) {
      float v = trbuf[tid];
      v += __shfl_xor_sync(0xffffu, v, 8);
      v += __shfl_xor_sync(0xffffu, v, 4);
      v += __shfl_xor_sync(0xffffu, v, 2);
      v += __shfl_xor_sync(0xffffu, v, 1);
      if (tid == 0) scal = 1.f / v;
    }
    __syncthreads();
    float invt = 0.5f * scal;
    #pragma unroll
    for (int u = 0; u < 16; u++) comacc[u] = fmaf(acc[u], invt, comacc[u]);
    __syncthreads();
  }
  if (tx == ty) {
    #pragma unroll
    for (int r = 0; r < 4; r++) comacc[r*4+r] += 1e-5f;
  }
  float* dst = g_com + (size_t)bid*CCH*PC;
  #pragma unroll
  for (int r = 0; r < 4; r++) {
    int j = ty*4 + r;
    if (j < CCH) {
      float4 v = make_float4(comacc[r*4+0], comacc[r*4+1], comacc[r*4+2], comacc[r*4+3]);
      *(float4*)(dst + j*PC + tx*4) = v;
    }
  }
}

// ---------------- K3: branch GEMMs (sigmoid) + attention ----------------
#define SM3_LW 0
#define SM3_COMS 4096
#define SM3_W1 8192
#define SM3_RS 8812
#define SM3_LB 8876
#define SM3_SB 8940
#define SM3_BB 9260
#define SM3_ZS 9580
#define SM3_BYTES (SM3_ZS*4 + NBAND*HW*2)   // 76760 bytes

__global__ __launch_bounds__(NTH) void branch_kernel(
    const float* __restrict__ hlin_w, const float* __restrict__ hlin_b,
    const float* __restrict__ hconv_w, const float* __restrict__ hconv_b,
    const float* __restrict__ elin_w, const float* __restrict__ elin_b,
    const float* __restrict__ econv_w, const float* __restrict__ econv_b,
    const float* __restrict__ att_w1, const float* __restrict__ att_b1,
    const float* __restrict__ att_w2) {
  extern __shared__ float sm3[];
  float* lw = sm3 + SM3_LW;
  float* coms = sm3 + SM3_COMS;
  float* w1s = sm3 + SM3_W1;
  float* rowsum = sm3 + SM3_RS;
  float* lbb = sm3 + SM3_LB;
  float* sbuf = sm3 + SM3_SB;
  float* bbuf = sm3 + SM3_BB;
  __half* zs = (__half*)(sm3 + SM3_ZS);

  int bid = blockIdx.x;
  int branch = bid & 1, b = bid >> 1;
  int tid = threadIdx.x, tx = tid & 15, ty = tid >> 4;

  const float* lin_w = branch ? elin_w : hlin_w;
  const float* lin_b = branch ? elin_b : hlin_b;
  const float* cw = branch ? econv_w : hconv_w;
  const float* cb = branch ? econv_b : hconv_b;

  for (int i = tid; i < 4096; i += NTH) lw[i] = 0.f;
  if (tid < 128) coms[3968 + tid] = 0.f;
  for (int i = tid; i < 620; i += NTH) w1s[i] = att_w1[i];
  __syncthreads();
  for (int i = tid; i < CCH*CCH; i += NTH) {
    int o = i / CCH, c = i - o*CCH;
    lw[o*PC + c] = lin_w[i];
  }
  if (tid < CCH) lbb[tid] = lin_b[tid];
  __syncthreads();
  if (tid < CCH) {
    float s = 0.f;
    #pragma unroll 2
    for (int c = 0; c < CCH; c++) s += lw[tid*PC + c];
    rowsum[tid] = s;
  }
  __syncthreads();

  for (int k = 0; k < NBAND; k++) {
    const float4* src = (const float4*)(g_com + (size_t)(b*NBAND + k)*CCH*PC);
    for (int e = tid; e < 992; e += NTH) ((float4*)coms)[e] = src[e];
    __syncthreads();
    float cwk = cw[k], cbk = cb[k];
    float acc[16];
    #pragma unroll
    for (int u = 0; u < 16; u++) acc[u] = 0.f;
    #pragma unroll 4
    for (int c0 = 0; c0 < PC; c0 += 4) {
      float4 a[4], bb4[4];
      #pragma unroll
      for (int r = 0; r < 4; r++) a[r] = *(const float4*)(coms + (ty*4+r)*PC + c0);
      #pragma unroll
      for (int q = 0; q < 4; q++) bb4[q] = *(const float4*)(lw + (tx*4+q)*PC + c0);
      #pragma unroll
      for (int r = 0; r < 4; r++) {
        #pragma unroll
        for (int q = 0; q < 4; q++) {
          acc[r*4+q] = fmaf(a[r].x, bb4[q].x, acc[r*4+q]);
          acc[r*4+q] = fmaf(a[r].y, bb4[q].y, acc[r*4+q]);
          acc[r*4+q] = fmaf(a[r].z, bb4[q].z, acc[r*4+q]);
          acc[r*4+q] = fmaf(a[r].w, bb4[q].w, acc[r*4+q]);
        }
      }
    }
    #pragma unroll
    for (int r = 0; r < 4; r++) {
      int i = ty*4 + r;
      if (i < CCH) {
        #pragma unroll
        for (int q = 0; q < 4; q++) {
          int o = tx*4 + q;
          if (o < CCH) {
            float zz = cwk*acc[r*4+q] + cbk*rowsum[o] + lbb[o];
            zs[k*HW + i*CCH + o] = __float2half(sigmoidf_(zz));
          }
        }
      }
    }
    __syncthreads();
  }

  for (int rr = tid; rr < NBAND*CCH; rr += NTH) {
    int k = rr / CCH, i = rr - k*CCH;
    const __half* zrow = zs + k*HW + i*CCH;
    float hacc[10];
    #pragma unroll
    for (int t = 0; t < 10; t++) hacc[t] = 0.f;
    for (int c = 0; c < CCH; c++) {
      float zv = __half2float(zrow[c]);
      #pragma unroll
      for (int t = 0; t < 10; t++) hacc[t] = fmaf(zv, w1s[t*CCH + c], hacc[t]);
    }
    float sc = 0.f;
    #pragma unroll
    for (int t = 0; t < 10; t++) sc = fmaf(tanhf(hacc[t] + att_b1[t]), att_w2[t], sc);
    sbuf[k*PC + i] = sc;
  }
  __syncthreads();
  if (tid < CCH) {
    float s[NBAND], m = -1e30f;
    #pragma unroll
    for (int k = 0; k < NBAND; k++) { s[k] = sbuf[k*PC + tid]; m = fmaxf(m, s[k]); }
    float ssum = 0.f;
    #pragma unroll
    for (int k = 0; k < NBAND; k++) { s[k] = expf(s[k] - m); ssum += s[k]; }
    float inv = 1.f/ssum;
    #pragma unroll
    for (int k = 0; k < NBAND; k++) bbuf[k*PC + tid] = s[k]*inv;
  }
  __syncthreads();
  float* dst = g_att + (size_t)bid*HW;
  for (int idx = tid; idx < HW; idx += NTH) {
    int i = idx / CCH, c = idx - i*CCH;
    float a = 0.f;
    #pragma unroll
    for (int k = 0; k < NBAND; k++)
      a = fmaf(bbuf[k*PC + i], __half2float(zs[k*HW + i*CCH + c]), a);
    dst[idx] = a;
  }
}

// ---------------- K4: Chebyshev GCN + fc ----------------
__global__ __launch_bounds__(NTH) void gcn_kernel(
    const float* __restrict__ de, const float* __restrict__ gc_w,
    const float* __restrict__ gc_b, const float* __restrict__ fc_w,
    const float* __restrict__ fc_b) {
  __shared__ float hbuf[HW];
  __shared__ float ebuf[HW];
  __shared__ float debuf[CCH*NBAND];
  __shared__ float xg0[CCH*NOUT];
  __shared__ float xg1[CCH*NOUT];
  __shared__ float fbuf[CCH*NOUT];
  int b = blockIdx.x, tid = threadIdx.x;

  const float4* hs = (const float4*)(g_att + (size_t)(b*2)*HW);
  const float4* es = (const float4*)(g_att + (size_t)(b*2+1)*HW);
  for (int e = tid; e < HW/4; e += NTH) {
    ((float4*)hbuf)[e] = hs[e];
    ((float4*)ebuf)[e] = es[e];
  }
  for (int i = tid; i < CCH*NBAND; i += NTH) debuf[i] = de[(size_t)b*CCH*NBAND + i];
  __syncthreads();
  for (int idx = tid; idx < CCH*NOUT; idx += NTH) {
    int i = idx >> 4, f = idx & 15;
    float a0 = 0.f, a1 = 0.f;
    #pragma unroll
    for (int t = 0; t < NBAND; t++) {
      float dv = debuf[i*NBAND + t];
      a0 = fmaf(dv, gc_w[t*NOUT + f], a0);
      a1 = fmaf(dv, gc_w[(NBAND + t)*NOUT + f], a1);
    }
    xg0[idx] = a0 + gc_b[f] + gc_b[NOUT + f];
    xg1[idx] = a1;
  }
  __syncthreads();
  for (int idx = tid; idx < CCH*NOUT; idx += NTH) {
    int i = idx >> 4, f = idx & 15;
    float ah = 0.f, ae = 0.f;
    #pragma unroll 2
    for (int j = 0; j < CCH; j++) {
      float v = xg1[j*NOUT + f];
      ah = fmaf(hbuf[i*CCH + j], v, ah);
      ae = fmaf(ebuf[i*CCH + j], v, ae);
    }
    float base = xg0[idx];
    float hv = fmaxf(base + ah, 0.f);
    float ev = fmaxf(base + ae, 0.f);
    fbuf[idx] = 0.5f*(hv + ev);
  }
  __syncthreads();
  int w = tid >> 5, l = tid & 31;
  #pragma unroll
  for (int t = 0; t < 8; t++) {
    int o = w*8 + t;
    if (o < CCH) {
      float acc = 0.f;
      const float* wrow = fc_w + (size_t)o*(CCH*NOUT);
      for (int m = l; m < CCH*NOUT; m += 32) acc = fmaf(fbuf[m], wrow[m], acc);
      acc += __shfl_xor_sync(0xffffffffu, acc, 16);
      acc += __shfl_xor_sync(0xffffffffu, acc, 8);
      acc += __shfl_xor_sync(0xffffffffu, acc, 4);
      acc += __shfl_xor_sync(0xffffffffu, acc, 2);
      acc += __shfl_xor_sync(0xffffffffu, acc, 1);
      if (l == 0) g_z[b*CCH + o] = acc + fc_b[o];
    }
  }
}

// ---------------- K5: BN stats over batch ----------------
__global__ __launch_bounds__(NTH) void stats_kernel() {
  __shared__ double rs[NTH], rs2[NTH];
  int c = blockIdx.x, tid = threadIdx.x;
  double s = 0.0, s2 = 0.0;
  for (int bb = tid; bb < NB; bb += NTH) {
    double v = (double)g_z[bb*CCH + c];
    s += v; s2 += v*v;
  }
  rs[tid] = s; rs2[tid] = s2;
  __syncthreads();
  for (int off = NTH/2; off > 0; off >>= 1) {
    if (tid < off) { rs[tid] += rs[tid+off]; rs2[tid] += rs2[tid+off]; }
    __syncthreads();
  }
  if (tid == 0) {
    double m = rs[0] / NB;
    double var = rs2[0] / NB - m*m;
    g_stats[c] = (float)m;
    g_stats[64 + c] = (float)(1.0 / sqrt(var + 1e-5));
  }
}

// ---------------- K6: normalize + sigmoid + head ----------------
__global__ __launch_bounds__(64) void final_kernel(
    const float* __restrict__ bn_g, const float* __restrict__ bn_b,
    const float* __restrict__ fc4_w, const float* __restrict__ fc4_b,
    float* __restrict__ out) {
  __shared__ float o1[64];
  int b = blockIdx.x, tid = threadIdx.x;
  if (tid < CCH) {
    float z = g_z[b*CCH + tid];
    float zn = (z - g_stats[tid]) * g_stats[64 + tid] * bn_g[tid] + bn_b[tid];
    float v = sigmoidf_(zn);
    out[b*CCH + tid] = v;
    o1[tid] = v;
  }
  __syncthreads();
  if (tid < 2) {
    float acc = fc4_b[tid];
    #pragma unroll 2
    for (int c = 0; c < CCH; c++) acc = fmaf(o1[c], fc4_w[tid*CCH + c], acc);
    out[NB*CCH + b*2 + tid] = acc;
  }
}

extern "C" void kernel_launch(void* const* d_in, const int* in_sizes, int n_in,
                              void* d_out, int out_size) {
  const float* de     = (const float*)d_in[0];
  const float* pcc    = (const float*)d_in[1];
  const float* Aadj   = (const float*)d_in[2];
  const float* conv_w = (const float*)d_in[3];
  const float* conv_b = (const float*)d_in[4];
  const float* hconv_w= (const float*)d_in[5];
  const float* hconv_b= (const float*)d_in[6];
  const float* hlin_w = (const float*)d_in[7];
  const float* hlin_b = (const float*)d_in[8];
  const float* econv_w= (const float*)d_in[9];
  const float* econv_b= (const float*)d_in[10];
  const float* elin_w = (const float*)d_in[11];
  const float* elin_b = (const float*)d_in[12];
  const float* att_w1 = (const float*)d_in[13];
  const float* att_b1 = (const float*)d_in[14];
  const float* att_w2 = (const float*)d_in[15];
  const float* gc_w   = (const float*)d_in[16];
  const float* gc_b   = (const float*)d_in[17];
  /* d_in[18] = wpar: softmax over a single element == 1, folded out */
  const float* fc_w   = (const float*)d_in[19];
  const float* fc_b   = (const float*)d_in[20];
  const float* bn_g   = (const float*)d_in[21];
  const float* bn_b   = (const float*)d_in[22];
  const float* fc4_w  = (const float*)d_in[23];
  const float* fc4_b  = (const float*)d_in[24];

  cudaFuncSetAttribute(branch_kernel, cudaFuncAttributeMaxDynamicSharedMemorySize, SM3_BYTES);

  permw_kernel<<<(NBAND*NELEM + NTH - 1)/NTH, NTH>>>(conv_w);
  gate_kernel<<<NB, NTH>>>(Aadj, pcc, conv_w, conv_b);
  com_kernel<<<NB*NBAND, NTH>>>(Aadj, pcc);
  branch_kernel<<<NB*2, NTH, SM3_BYTES>>>(hlin_w, hlin_b, hconv_w, hconv_b,
                                          elin_w, elin_b, econv_w, econv_b,
                                          att_w1, att_b1, att_w2);
  gcn_kernel<<<NB, NTH>>>(de, gc_w, gc_b, fc_w, fc_b);
  stats_kernel<<<CCH, NTH>>>();
  final_kernel<<<NB, 64>>>(bn_g, bn_b, fc4_w, fc4_b, (float*)d_out);
}